// round 3
// baseline (speedup 1.0000x reference)
#include <cuda_runtime.h>

// OpeningLoss2D: mean((labels - grey_opening(labels, size=2))^2)
// labels: [B, C, 512, 512] fp32 (B*C derived from in_sizes[0]); out: 1 fp32 scalar.
//
// size=2 => erosion offsets [-1,0], dilation offsets [0,+1], symmetric (edge-clamp) padding.
// Separable: rmin (x-min pair) -> er (y-min pair) -> di (2x2 max with clamped +1 indices).
// NOTE: dilation pads er itself, so at y==H-1 the y+1 term is the true er[H-1]
// (min of rmin rows H-2,H-1), NOT an er built from a duplicated lab row.

#define H 512
#define W 512
#define TY 16
#define BANDS (H / TY)        // 32
#define TROWS (TY + 2)        // 18 (band + 1 halo row each side)
#define W4 (W / 4)            // 128
#define NTHREADS 256
#define MAX_BLOCKS 8192

__device__ double g_partials[MAX_BLOCKS];

__global__ __launch_bounds__(NTHREADS)
void opening_loss_main(const float* __restrict__ lab)
{
    __shared__ float s_rmin[TROWS * W];          // 36,864 B
    __shared__ float s_wsum[NTHREADS / 32];

    const int img  = blockIdx.y;
    const int band = blockIdx.x;
    const int r0   = band * TY;
    const float* base = lab + (size_t)img * H * W;
    const int tid = threadIdx.x;

    float4* s_rmin4 = (float4*)s_rmin;

    // ---- Stage 1: x-direction row-min into shared (18 rows, clamped) ----
    // 18*128 = 2304 float4 tasks / 256 threads = 9 per thread (independent -> high MLP)
    #pragma unroll
    for (int it = 0; it < (TROWS * W4) / NTHREADS; it++) {
        int i   = it * NTHREADS + tid;
        int row = i >> 7;           // / W4
        int c4  = i & (W4 - 1);
        int gr  = r0 - 1 + row;
        gr = max(0, min(gr, H - 1));
        const float* rp = base + (size_t)gr * W;
        float4 v = ((const float4*)rp)[c4];
        float left = (c4 == 0) ? v.x : rp[c4 * 4 - 1];   // symmetric pad == edge clamp
        float4 r;
        r.x = fminf(left, v.x);
        r.y = fminf(v.x,  v.y);
        r.z = fminf(v.y,  v.z);
        r.w = fminf(v.z,  v.w);
        s_rmin4[row * W4 + c4] = r;
    }
    __syncthreads();

    // ---- Stage 2: y-erosion + 2x2 dilation + squared-diff accumulate ----
    float acc = 0.f;
    #pragma unroll
    for (int it = 0; it < (TY * W4) / NTHREADS; it++) {   // 8 per thread
        int i    = it * NTHREADS + tid;
        int orow = i >> 7;
        int c4   = i & (W4 - 1);
        int tr   = orow + 1;            // tile row of this output
        int gy   = r0 + orow;           // global row

        float4 am1 = s_rmin4[(tr - 1) * W4 + c4];
        float4 a0  = s_rmin4[(tr    ) * W4 + c4];
        float4 ap1 = s_rmin4[(tr + 1) * W4 + c4];
        // next-column scalars (x+4), clamped at W-1
        float nm1 = (c4 < W4 - 1) ? s_rmin4[(tr - 1) * W4 + c4 + 1].x : am1.w;
        float n0  = (c4 < W4 - 1) ? s_rmin4[(tr    ) * W4 + c4 + 1].x : a0.w;
        float np1 = (c4 < W4 - 1) ? s_rmin4[(tr + 1) * W4 + c4 + 1].x : ap1.w;

        // dilation bottom clamp: er[y+1] -> er[y] == min(rmin[y-1], rmin[y])
        if (gy == H - 1) { ap1 = am1; np1 = nm1; }

        // labels re-read: same block just loaded these -> L1 hit, no extra DRAM
        float4 lv = ((const float4*)(base + (size_t)gy * W))[c4];

        float xm1[5] = {am1.x, am1.y, am1.z, am1.w, nm1};
        float x0 [5] = {a0.x,  a0.y,  a0.z,  a0.w,  n0 };
        float xp1[5] = {ap1.x, ap1.y, ap1.z, ap1.w, np1};
        float lvv[4] = {lv.x, lv.y, lv.z, lv.w};

        #pragma unroll
        for (int j = 0; j < 4; j++) {
            float ert  = fminf(xm1[j],     x0[j]);       // er[y][x]
            float ertn = fminf(xm1[j + 1], x0[j + 1]);   // er[y][x+1]
            float erb  = fminf(x0[j],      xp1[j]);      // er[y+1][x]
            float erbn = fminf(x0[j + 1],  xp1[j + 1]);  // er[y+1][x+1]
            float di = fmaxf(fmaxf(ert, ertn), fmaxf(erb, erbn));
            float d  = lvv[j] - di;
            acc = fmaf(d, d, acc);
        }
    }

    // ---- Block reduction -> per-block double partial (no atomics: deterministic) ----
    #pragma unroll
    for (int o = 16; o; o >>= 1)
        acc += __shfl_xor_sync(0xFFFFFFFFu, acc, o);
    if ((tid & 31) == 0) s_wsum[tid >> 5] = acc;
    __syncthreads();
    if (tid == 0) {
        float s = 0.f;
        #pragma unroll
        for (int w = 0; w < NTHREADS / 32; w++) s += s_wsum[w];
        g_partials[blockIdx.y * gridDim.x + blockIdx.x] = (double)s;
    }
}

__global__ void opening_loss_finalize(float* __restrict__ out, int nblocks, double inv_n)
{
    __shared__ double sh[256];
    double s = 0.0;
    for (int i = threadIdx.x; i < nblocks; i += 256)
        s += g_partials[i];
    sh[threadIdx.x] = s;
    __syncthreads();
    #pragma unroll
    for (int o = 128; o; o >>= 1) {
        if (threadIdx.x < o) sh[threadIdx.x] += sh[threadIdx.x + o];
        __syncthreads();
    }
    if (threadIdx.x == 0) out[0] = (float)(sh[0] * inv_n);
}

extern "C" void kernel_launch(void* const* d_in, const int* in_sizes, int n_in,
                              void* d_out, int out_size)
{
    const float* lab = (const float*)d_in[0];
    const int n      = in_sizes[0];
    const int n_img  = n / (H * W);           // B*C (128 for the reference shapes)
    const int nblk   = n_img * BANDS;

    dim3 grid(BANDS, n_img);
    opening_loss_main<<<grid, NTHREADS>>>(lab);
    opening_loss_finalize<<<1, 256>>>((float*)d_out, nblk, 1.0 / (double)n);
}

// round 9
// speedup vs baseline: 1.0081x; 1.0081x over previous
#include <cuda_runtime.h>

// OpeningLoss2D: mean((labels - grey_opening(labels, size=2))^2)
// labels: [B, C, 512, 512] fp32; out: 1 fp32 scalar.
//
// size=2 => erosion offsets [-1,0], dilation offsets [0,+1], symmetric (edge-clamp) pad.
// Separable: rmin (x-min pair) -> er (y-min pair) -> di (2x2 max, clamped +1 indices).
// Dilation pads er itself: at y==H-1 the y+1 term is the TRUE er[H-1]
// (min of rmin rows H-2,H-1)  -> substitute ap1 = am1 on the last row.
//
// vs R2 baseline (51.9us):
//  * labels kept in REGISTERS across stages (thread owns fixed c4, rows half+2r)
//    -> stage-2 global re-read eliminated; LTS traffic halved (was the binder).
//  * finalize kernel folded into main via last-block-done ticket -> one launch,
//    partials summed L2-hot instead of a 6.6us cold single-block kernel.
//  * no spin-waits anywhere: pattern cannot deadlock under graph replay.

#define H 512
#define W 512
#define TY 16
#define BANDS (H / TY)        // 32
#define TROWS (TY + 2)        // 18
#define W4 (W / 4)            // 128
#define NTHREADS 256
#define MAX_BLOCKS 8192

__device__ double g_partials[MAX_BLOCKS];
__device__ int    g_ticket;           // zero-init at load; self-resets each call

__global__ __launch_bounds__(NTHREADS)
void opening_loss_fused(const float* __restrict__ lab, float* __restrict__ out,
                        int nblk, double inv_n)
{
    __shared__ float  s_rmin[TROWS * W];         // 36,864 B
    __shared__ float  s_wsum[NTHREADS / 32];
    __shared__ int    s_islast;
    __shared__ double s_dsum[NTHREADS];

    const int img  = blockIdx.y;
    const int band = blockIdx.x;
    const int r0   = band * TY;
    const float* base = lab + (size_t)img * H * W;
    const int tid  = threadIdx.x;
    const int half = tid >> 7;          // 0: even tile rows, 1: odd tile rows
    const int c4   = tid & (W4 - 1);    // fixed column (float4 index)

    float4* s_rmin4 = (float4*)s_rmin;

    // ---- Stage 1: x row-min into shared; labels stay in registers ----
    // thread covers tile rows tr = half + 2r, r=0..8  (18 rows across the block)
    float4 v[9];
    #pragma unroll
    for (int r = 0; r < 9; r++) {
        int tr = half + 2 * r;                   // 0..17
        int gr = r0 - 1 + tr;
        gr = max(0, min(gr, H - 1));             // symmetric pad == edge clamp (y)
        const float* rp = base + (size_t)gr * W;
        v[r] = ((const float4*)rp)[c4];
        float left = (c4 == 0) ? v[r].x : rp[c4 * 4 - 1];  // edge clamp (x)
        float4 m;
        m.x = fminf(left,   v[r].x);
        m.y = fminf(v[r].x, v[r].y);
        m.z = fminf(v[r].y, v[r].z);
        m.w = fminf(v[r].z, v[r].w);
        s_rmin4[tr * W4 + c4] = m;
    }
    __syncthreads();

    // ---- Stage 2: y-erosion + 2x2 dilation + squared diff (labels from regs) ----
    float acc = 0.f;
    #pragma unroll
    for (int r = 0; r < 9; r++) {
        int tr = half + 2 * r;                   // output tile rows are 1..16
        if (tr < 1 || tr > TY) continue;
        int gy = r0 + tr - 1;                    // == the unclamped gr of v[r]

        float4 am1 = s_rmin4[(tr - 1) * W4 + c4];
        float4 a0  = s_rmin4[(tr    ) * W4 + c4];
        float4 ap1 = s_rmin4[(tr + 1) * W4 + c4];
        float nm1 = (c4 < W4 - 1) ? s_rmin4[(tr - 1) * W4 + c4 + 1].x : am1.w;
        float n0  = (c4 < W4 - 1) ? s_rmin4[(tr    ) * W4 + c4 + 1].x : a0.w;
        float np1 = (c4 < W4 - 1) ? s_rmin4[(tr + 1) * W4 + c4 + 1].x : ap1.w;

        if (gy == H - 1) { ap1 = am1; np1 = nm1; }   // dilation bottom clamp on er

        float xm1[5] = {am1.x, am1.y, am1.z, am1.w, nm1};
        float x0 [5] = {a0.x,  a0.y,  a0.z,  a0.w,  n0 };
        float xp1[5] = {ap1.x, ap1.y, ap1.z, ap1.w, np1};
        float lvv[4] = {v[r].x, v[r].y, v[r].z, v[r].w};

        #pragma unroll
        for (int j = 0; j < 4; j++) {
            float ert  = fminf(xm1[j],     x0[j]);
            float ertn = fminf(xm1[j + 1], x0[j + 1]);
            float erb  = fminf(x0[j],      xp1[j]);
            float erbn = fminf(x0[j + 1],  xp1[j + 1]);
            float di = fmaxf(fmaxf(ert, ertn), fmaxf(erb, erbn));
            float d  = lvv[j] - di;
            acc = fmaf(d, d, acc);
        }
    }

    // ---- Block reduction -> per-block double partial ----
    #pragma unroll
    for (int o = 16; o; o >>= 1)
        acc += __shfl_xor_sync(0xFFFFFFFFu, acc, o);
    if ((tid & 31) == 0) s_wsum[tid >> 5] = acc;
    __syncthreads();

    const int myblk = blockIdx.y * gridDim.x + blockIdx.x;
    if (tid == 0) {
        float s = 0.f;
        #pragma unroll
        for (int w = 0; w < NTHREADS / 32; w++) s += s_wsum[w];
        g_partials[myblk] = (double)s;
        __threadfence();                          // partial visible before ticket
        int t = atomicAdd(&g_ticket, 1);
        s_islast = (t == nblk - 1);
    }
    __syncthreads();

    // ---- Last block: sum all partials (L2-hot) and write the scalar ----
    if (s_islast) {
        double s = 0.0;
        for (int i = tid; i < nblk; i += NTHREADS)   // fixed order -> deterministic
            s += g_partials[i];
        s_dsum[tid] = s;
        __syncthreads();
        #pragma unroll
        for (int o = NTHREADS / 2; o; o >>= 1) {
            if (tid < o) s_dsum[tid] += s_dsum[tid + o];
            __syncthreads();
        }
        if (tid == 0) {
            out[0] = (float)(s_dsum[0] * inv_n);
            g_ticket = 0;                         // reset for next graph replay
        }
    }
}

extern "C" void kernel_launch(void* const* d_in, const int* in_sizes, int n_in,
                              void* d_out, int out_size)
{
    const float* lab = (const float*)d_in[0];
    const int n      = in_sizes[0];
    const int n_img  = n / (H * W);               // 128 for [16,8,512,512]
    const int nblk   = n_img * BANDS;             // 4096

    dim3 grid(BANDS, n_img);
    opening_loss_fused<<<grid, NTHREADS>>>(lab, (float*)d_out, nblk, 1.0 / (double)n);
}